// round 1
// baseline (speedup 1.0000x reference)
#include <cuda_runtime.h>
#include <cuda_bf16.h>
#include <cstdint>
#include <cstdio>

// Problem constants
#define NU 50000
#define NI 50000
#define FH 128
#define EC 800000
#define GC 512
#define CC 16
#define LC 3
#define BN_EPS 1e-5f

// ---------------------------------------------------------------------------
// Scratch: one big __device__ global (allocation-free rule).
// Layout (floats):
//   [0..NODE)        xu ping
//   [NODE..2N)       xu pong
//   [2N..3N)         xi ping
//   [3N..4N)         xi pong
//   [4N..5N)         agg_u
//   [5N..6N)         agg_i     (contiguous with agg_u -> one zero pass)
//   [6N..7N)         new_u
//   [7N..8N)         new_i
//   small region: cnt(512), inv(512), stats(512: sum_u,sq_u,sum_i,sq_i),
//                 bn(512: scale_u,shift_u,scale_i,shift_i)
// ---------------------------------------------------------------------------
#define NODEF (50000ull * 128ull)              // 6,400,000 floats
#define OFF_XU0 (0ull)
#define OFF_XU1 (1ull * NODEF)
#define OFF_XI0 (2ull * NODEF)
#define OFF_XI1 (3ull * NODEF)
#define OFF_AGU (4ull * NODEF)
#define OFF_AGI (5ull * NODEF)
#define OFF_NWU (6ull * NODEF)
#define OFF_NWI (7ull * NODEF)
#define OFF_CNT (8ull * NODEF)
#define OFF_INV (OFF_CNT + 512ull)
#define OFF_STATS (OFF_INV + 512ull)
#define OFF_BN (OFF_STATS + 512ull)
#define BUF_TOTAL (OFF_BN + 512ull)

__device__ float g_buf[BUF_TOTAL];

// ---------------------------------------------------------------------------
// Vectorized global reduction (sm_90+): 4 floats per instruction.
// ---------------------------------------------------------------------------
__device__ __forceinline__ void red_add_v4(float* addr, float4 v) {
    asm volatile("red.global.add.v4.f32 [%0], {%1,%2,%3,%4};"
                 :: "l"(addr), "f"(v.x), "f"(v.y), "f"(v.z), "f"(v.w)
                 : "memory");
}

// ---------------------------------------------------------------------------
// Zero a float buffer (n4 = count of float4)
// ---------------------------------------------------------------------------
__global__ void k_zero(float* __restrict__ p, int n4) {
    int t = blockIdx.x * blockDim.x + threadIdx.x;
    if (t < n4) reinterpret_cast<float4*>(p)[t] = make_float4(0.f, 0.f, 0.f, 0.f);
}

// ---------------------------------------------------------------------------
// Per-group node counts (users + items share the same group histogram)
// ---------------------------------------------------------------------------
__global__ void k_count(const int* __restrict__ bu, const int* __restrict__ bi,
                        float* __restrict__ cnt) {
    int t = blockIdx.x * blockDim.x + threadIdx.x;
    if (t < NU) {
        atomicAdd(&cnt[bu[t]], 1.0f);
    } else {
        int j = t - NU;
        if (j < NI) atomicAdd(&cnt[bi[j]], 1.0f);
    }
}

__global__ void k_invcnt(const float* __restrict__ cnt, float* __restrict__ inv) {
    int t = threadIdx.x;
    if (t < GC) inv[t] = 1.0f / fmaxf(cnt[t], 1.0f);
}

// ---------------------------------------------------------------------------
// Edge scatter: agg[dst] += x[src], 32 lanes/edge, float4 per lane, L2 red.v4
// edge layout: [0..E) = src indices, [E..2E) = dst indices
// ---------------------------------------------------------------------------
__global__ void k_scatter(const float* __restrict__ xsrc, const int* __restrict__ edge,
                          float* __restrict__ agg) {
    int t = blockIdx.x * blockDim.x + threadIdx.x;
    int e = t >> 5;
    int lane = t & 31;
    if (e >= EC) return;
    int src = edge[e];
    int dst = edge[EC + e];
    float4 v = *reinterpret_cast<const float4*>(&xsrc[(size_t)src * FH + lane * 4]);
    red_add_v4(&agg[(size_t)dst * FH + lane * 4], v);
}

// ---------------------------------------------------------------------------
// Fused GraphConv GEMM: out[n,h] = sum_f A[n,f]*Wa[h,f] + sum_f X[n,f]*Wb[h,f] + bias[h]
// Tile: 64 rows x 128 cols, K split 8 x 32 (first half from A/Wa, second X/Wb).
// 256 threads, each computes 8x4 outputs. Full fp32.
// ---------------------------------------------------------------------------
__global__ void __launch_bounds__(256) k_gemm(
    const float* __restrict__ A, const float* __restrict__ X,
    const float* __restrict__ Wa, const float* __restrict__ Wb,
    const float* __restrict__ bias, float* __restrict__ out, int nrows) {
    __shared__ float sA[64][32];     // [row][k]
    __shared__ float sW[32][132];    // [k][h], padded (132*4 % 16 == 0 -> float4 OK)

    int row0 = blockIdx.x * 64;
    int tid = threadIdx.x;
    int tx = tid & 31;   // column group: h = tx*4 .. tx*4+3
    int ty = tid >> 5;   // row group: rows ty*8 .. ty*8+7

    float acc[8][4];
#pragma unroll
    for (int i = 0; i < 8; i++)
#pragma unroll
        for (int j = 0; j < 4; j++) acc[i][j] = 0.f;

    for (int kt = 0; kt < 8; kt++) {
        const float* Ap = (kt < 4) ? A : X;
        const float* Wp = (kt < 4) ? Wa : Wb;
        int f0 = (kt & 3) * 32;

        // Load A chunk: 64x32 = 512 float4, 2 per thread
#pragma unroll
        for (int i = 0; i < 2; i++) {
            int idx = tid * 2 + i;        // 0..511
            int r = idx >> 3;
            int c4 = idx & 7;
            float4 v = make_float4(0.f, 0.f, 0.f, 0.f);
            if (row0 + r < nrows)
                v = *reinterpret_cast<const float4*>(
                    &Ap[(size_t)(row0 + r) * FH + f0 + c4 * 4]);
            *reinterpret_cast<float4*>(&sA[r][c4 * 4]) = v;
        }
        // Load W chunk transposed: sW[k][h] = Wp[h][f0+k]; 128x32 floats, 1 float4/thr x4
#pragma unroll
        for (int i = 0; i < 4; i++) {
            int idx = tid * 4 + i;        // 0..1023
            int h = idx >> 3;
            int c4 = idx & 7;
            float4 v = *reinterpret_cast<const float4*>(&Wp[h * FH + f0 + c4 * 4]);
            sW[c4 * 4 + 0][h] = v.x;
            sW[c4 * 4 + 1][h] = v.y;
            sW[c4 * 4 + 2][h] = v.z;
            sW[c4 * 4 + 3][h] = v.w;
        }
        __syncthreads();

#pragma unroll
        for (int k = 0; k < 32; k++) {
            float4 w = *reinterpret_cast<const float4*>(&sW[k][tx * 4]);
#pragma unroll
            for (int i = 0; i < 8; i++) {
                float a = sA[ty * 8 + i][k];   // warp-broadcast
                acc[i][0] += a * w.x;
                acc[i][1] += a * w.y;
                acc[i][2] += a * w.z;
                acc[i][3] += a * w.w;
            }
        }
        __syncthreads();
    }

    float4 b = *reinterpret_cast<const float4*>(&bias[tx * 4]);
#pragma unroll
    for (int i = 0; i < 8; i++) {
        int r = row0 + ty * 8 + i;
        if (r < nrows) {
            float4 v = make_float4(acc[i][0] + b.x, acc[i][1] + b.y,
                                   acc[i][2] + b.z, acc[i][3] + b.w);
            *reinterpret_cast<float4*>(&out[(size_t)r * FH + tx * 4]) = v;
        }
    }
}

// ---------------------------------------------------------------------------
// BN statistics over relu(new): per-column sum and sum-of-squares
// ---------------------------------------------------------------------------
__global__ void k_stats(const float* __restrict__ v, float* __restrict__ sum,
                        float* __restrict__ sq, int n) {
    int h = threadIdx.x;                 // 128
    int r0 = blockIdx.x * 128;
    int rend = min(r0 + 128, n);
    float s = 0.f, q = 0.f;
    for (int r = r0; r < rend; r++) {
        float x = fmaxf(v[(size_t)r * FH + h], 0.f);
        s += x;
        q += x * x;
    }
    atomicAdd(&sum[h], s);
    atomicAdd(&sq[h], q);
}

__global__ void k_bnparams(const float* __restrict__ sum, const float* __restrict__ sq,
                           const float* __restrict__ gamma, const float* __restrict__ beta,
                           float* __restrict__ scale, float* __restrict__ shift, float n) {
    int h = threadIdx.x;
    if (h < FH) {
        float invn = 1.0f / n;
        float m = sum[h] * invn;
        float var = sq[h] * invn - m * m;
        float s = gamma[h] * rsqrtf(var + BN_EPS);
        scale[h] = s;
        shift[h] = beta[h] - m * s;
    }
}

// ---------------------------------------------------------------------------
// Apply relu+BN, write next-layer features, and accumulate group-mean pool
// directly into the output feats region (pre-scaled by 1/cnt).
// ---------------------------------------------------------------------------
__global__ void k_apply_pool(const float* __restrict__ newv, const float* __restrict__ scale,
                             const float* __restrict__ shift, const int* __restrict__ batch,
                             const float* __restrict__ invcnt, float* __restrict__ xout,
                             float* __restrict__ pooled, int n) {
    int t = blockIdx.x * blockDim.x + threadIdx.x;
    if (t >= n * 32) return;
    int r = t >> 5;
    int lane = t & 31;
    int b = batch[r];
    float ic = invcnt[b];
    float4 x = *reinterpret_cast<const float4*>(&newv[(size_t)r * FH + lane * 4]);
    float4 sc = *reinterpret_cast<const float4*>(&scale[lane * 4]);
    float4 sh = *reinterpret_cast<const float4*>(&shift[lane * 4]);
    float4 y;
    y.x = fmaxf(x.x, 0.f) * sc.x + sh.x;
    y.y = fmaxf(x.y, 0.f) * sc.y + sh.y;
    y.z = fmaxf(x.z, 0.f) * sc.z + sh.z;
    y.w = fmaxf(x.w, 0.f) * sc.w + sh.w;
    *reinterpret_cast<float4*>(&xout[(size_t)r * FH + lane * 4]) = y;
    red_add_v4(&pooled[(size_t)b * FH + lane * 4],
               make_float4(y.x * ic, y.y * ic, y.z * ic, y.w * ic));
}

// ---------------------------------------------------------------------------
// Classifier heads: logits[l,g,c] = sum_h feats[l,g,h]*fcW[l,c,h] + fcb[l,c]
// ---------------------------------------------------------------------------
__global__ void k_logits(const float* __restrict__ feats, const float* __restrict__ fcW,
                         const float* __restrict__ fcb, float* __restrict__ out) {
    int lg = blockIdx.x;                 // 0..L*G-1
    int l = lg / GC;
    __shared__ float sf[FH];
    sf[threadIdx.x] = feats[(size_t)lg * FH + threadIdx.x];
    __syncthreads();
    int c = threadIdx.x;
    if (c < CC) {
        const float* w = &fcW[(size_t)(l * CC + c) * FH];
        float a = fcb[l * CC + c];
#pragma unroll 8
        for (int h = 0; h < FH; h++) a += sf[h] * w[h];
        out[(size_t)lg * CC + c] = a;
    }
}

// ---------------------------------------------------------------------------
extern "C" void kernel_launch(void* const* d_in, const int* in_sizes, int n_in,
                              void* d_out, int out_size) {
    const float* x_user    = (const float*)d_in[0];
    const float* x_item    = (const float*)d_in[1];
    const int*   e_u2i     = (const int*)d_in[2];
    const int*   e_i2u     = (const int*)d_in[3];
    const int*   b_user    = (const int*)d_in[4];
    const int*   b_item    = (const int*)d_in[5];
    const float* Wrel_u2i  = (const float*)d_in[6];
    const float* Wroot_u2i = (const float*)d_in[7];
    const float* bias_u2i  = (const float*)d_in[8];
    const float* Wrel_i2u  = (const float*)d_in[9];
    const float* Wroot_i2u = (const float*)d_in[10];
    const float* bias_i2u  = (const float*)d_in[11];
    const float* bng_u     = (const float*)d_in[12];
    const float* bnb_u     = (const float*)d_in[13];
    const float* bng_i     = (const float*)d_in[14];
    const float* bnb_i     = (const float*)d_in[15];
    const float* fcW       = (const float*)d_in[16];
    const float* fcb       = (const float*)d_in[17];
    float* out = (float*)d_out;

    float* buf = nullptr;
    cudaGetSymbolAddress((void**)&buf, g_buf);

    float* cnt     = buf + OFF_CNT;
    float* inv     = buf + OFF_INV;
    float* sum_u   = buf + OFF_STATS;
    float* sq_u    = sum_u + FH;
    float* sum_i   = sq_u + FH;
    float* sq_i    = sum_i + FH;
    float* scale_u = buf + OFF_BN;
    float* shift_u = scale_u + FH;
    float* scale_i = shift_u + FH;
    float* shift_i = scale_i + FH;

    float* agg_u = buf + OFF_AGU;
    float* agg_i = buf + OFF_AGI;
    float* new_u = buf + OFF_NWU;
    float* new_i = buf + OFF_NWI;

    const int OUT_ELEMS = LC * GC * CC + LC * GC * FH;   // 221184
    float* feats = out + LC * GC * CC;                   // +24576

    // Zero output (feats region is accumulated with reds) and group counts
    k_zero<<<(OUT_ELEMS / 4 + 255) / 256, 256>>>(out, OUT_ELEMS / 4);
    k_zero<<<1, 256>>>(cnt, GC / 4);
    k_count<<<(NU + NI + 255) / 256, 256>>>(b_user, b_item, cnt);
    k_invcnt<<<1, GC>>>(cnt, inv);

    const float* xu = x_user;
    const float* xi = x_item;

    for (int l = 0; l < LC; l++) {
        float* xu_n = buf + ((l & 1) ? OFF_XU1 : OFF_XU0);
        float* xi_n = buf + ((l & 1) ? OFF_XI1 : OFF_XI0);

        // Zero both agg buffers (contiguous: agg_u then agg_i)
        int nz4 = (int)(2ull * NODEF / 4ull);
        k_zero<<<(nz4 + 255) / 256, 256>>>(agg_u, nz4);

        // Scatter-add along both relations (reads previous-layer features)
        k_scatter<<<(EC * 32) / 256, 256>>>(xu, e_u2i, agg_i);
        k_scatter<<<(EC * 32) / 256, 256>>>(xi, e_i2u, agg_u);

        // Fused GraphConv GEMMs
        k_gemm<<<(NI + 63) / 64, 256>>>(agg_i, xi, Wrel_u2i + l * FH * FH,
                                        Wroot_u2i + l * FH * FH, bias_u2i + l * FH,
                                        new_i, NI);
        k_gemm<<<(NU + 63) / 64, 256>>>(agg_u, xu, Wrel_i2u + l * FH * FH,
                                        Wroot_i2u + l * FH * FH, bias_i2u + l * FH,
                                        new_u, NU);

        // BN statistics (zero 4x128 stats first)
        k_zero<<<1, 256>>>(sum_u, 512 / 4);
        k_stats<<<(NU + 127) / 128, 128>>>(new_u, sum_u, sq_u, NU);
        k_stats<<<(NI + 127) / 128, 128>>>(new_i, sum_i, sq_i, NI);
        k_bnparams<<<1, FH>>>(sum_u, sq_u, bng_u, bnb_u, scale_u, shift_u, (float)NU);
        k_bnparams<<<1, FH>>>(sum_i, sq_i, bng_i, bnb_i, scale_i, shift_i, (float)NI);

        // relu + BN apply, write next features, accumulate group-mean pool
        float* fl = feats + (size_t)l * GC * FH;
        k_apply_pool<<<(NU * 32 + 255) / 256, 256>>>(new_u, scale_u, shift_u, b_user,
                                                     inv, xu_n, fl, NU);
        k_apply_pool<<<(NI * 32 + 255) / 256, 256>>>(new_i, scale_i, shift_i, b_item,
                                                     inv, xi_n, fl, NI);

        xu = xu_n;
        xi = xi_n;
    }

    k_logits<<<LC * GC, FH>>>(feats, fcW, fcb, out);
}

// round 3
// speedup vs baseline: 1.4042x; 1.4042x over previous
#include <cuda_runtime.h>
#include <cuda_bf16.h>
#include <cstdint>
#include <cstdio>

// Problem constants
#define NU 50000
#define NI 50000
#define FH 128
#define EC 800000
#define GC 512
#define CC 16
#define LC 3
#define BN_EPS 1e-5f
#define DEGCAP 96

// ---------------------------------------------------------------------------
// Scratch
// ---------------------------------------------------------------------------
#define NODEF (50000ull * 128ull)              // 6,400,000 floats
#define OFF_XU0 (0ull)
#define OFF_XU1 (1ull * NODEF)
#define OFF_XI0 (2ull * NODEF)
#define OFF_XI1 (3ull * NODEF)
#define OFF_AGU (4ull * NODEF)
#define OFF_AGI (5ull * NODEF)
#define OFF_NWU (6ull * NODEF)
#define OFF_NWI (7ull * NODEF)
#define OFF_CNT (8ull * NODEF)
#define OFF_INV (OFF_CNT + 512ull)
#define OFF_STATS (OFF_INV + 512ull)
#define OFF_BN (OFF_STATS + 512ull)
#define BUF_TOTAL (OFF_BN + 512ull)

__device__ float g_buf[BUF_TOTAL];
__device__ int g_deg[2 * 50000];               // [0..NU): item-dst? see usage
__device__ int g_csr[2ull * 50000ull * DEGCAP];

// ---------------------------------------------------------------------------
// f32x2 packed helpers (sm_10x)
// ---------------------------------------------------------------------------
__device__ __forceinline__ unsigned long long pk2(float lo, float hi) {
    unsigned long long r;
    asm("mov.b64 %0, {%1, %2};" : "=l"(r) : "f"(lo), "f"(hi));
    return r;
}
__device__ __forceinline__ void unpk2(unsigned long long v, float& lo, float& hi) {
    asm("mov.b64 {%0, %1}, %2;" : "=f"(lo), "=f"(hi) : "l"(v));
}
__device__ __forceinline__ void fma2(unsigned long long& d, unsigned long long a,
                                     unsigned long long b) {
    asm("fma.rn.f32x2 %0, %1, %2, %0;" : "+l"(d) : "l"(a), "l"(b));
}

__device__ __forceinline__ void red_add_v4(float* addr, float4 v) {
    asm volatile("red.global.add.v4.f32 [%0], {%1,%2,%3,%4};"
                 :: "l"(addr), "f"(v.x), "f"(v.y), "f"(v.z), "f"(v.w)
                 : "memory");
}

// ---------------------------------------------------------------------------
__global__ void k_zero(float* __restrict__ p, int n4) {
    int t = blockIdx.x * blockDim.x + threadIdx.x;
    if (t < n4) reinterpret_cast<float4*>(p)[t] = make_float4(0.f, 0.f, 0.f, 0.f);
}

__global__ void k_count(const int* __restrict__ bu, const int* __restrict__ bi,
                        float* __restrict__ cnt) {
    int t = blockIdx.x * blockDim.x + threadIdx.x;
    if (t < NU) {
        atomicAdd(&cnt[bu[t]], 1.0f);
    } else {
        int j = t - NU;
        if (j < NI) atomicAdd(&cnt[bi[j]], 1.0f);
    }
}

__global__ void k_invcnt(const float* __restrict__ cnt, float* __restrict__ inv) {
    int t = threadIdx.x;
    if (t < GC) inv[t] = 1.0f / fmaxf(cnt[t], 1.0f);
}

// ---------------------------------------------------------------------------
// CSR bucket build: for each edge, append src into dst's bucket.
// edge layout: [0..E) = src, [E..2E) = dst
// ---------------------------------------------------------------------------
__global__ void k_build(const int* __restrict__ edge, int* __restrict__ deg,
                        int* __restrict__ csr) {
    int e = blockIdx.x * blockDim.x + threadIdx.x;
    if (e >= EC) return;
    int src = edge[e];
    int dst = edge[EC + e];
    int pos = atomicAdd(&deg[dst], 1);
    if (pos < DEGCAP) csr[(size_t)dst * DEGCAP + pos] = src;
}

// ---------------------------------------------------------------------------
// Gather: agg[dst] = sum over bucket of x[src]. 32 lanes/node, float4/lane.
// Writes every row -> no pre-zero needed.
// ---------------------------------------------------------------------------
__global__ void k_gather(const float* __restrict__ x, const int* __restrict__ deg,
                         const int* __restrict__ csr, float* __restrict__ agg) {
    int t = blockIdx.x * blockDim.x + threadIdx.x;
    int node = t >> 5;
    int lane = t & 31;
    if (node >= 50000) return;
    int d = deg[node];
    if (d > DEGCAP) d = DEGCAP;
    const int* lst = csr + (size_t)node * DEGCAP;
    float ax = 0.f, ay = 0.f, az = 0.f, aw = 0.f;
    int j = 0;
    for (; j + 4 <= d; j += 4) {
        int s0 = lst[j], s1 = lst[j + 1], s2 = lst[j + 2], s3 = lst[j + 3];
        float4 v0 = *reinterpret_cast<const float4*>(&x[(size_t)s0 * FH + lane * 4]);
        float4 v1 = *reinterpret_cast<const float4*>(&x[(size_t)s1 * FH + lane * 4]);
        float4 v2 = *reinterpret_cast<const float4*>(&x[(size_t)s2 * FH + lane * 4]);
        float4 v3 = *reinterpret_cast<const float4*>(&x[(size_t)s3 * FH + lane * 4]);
        ax += v0.x + v1.x + v2.x + v3.x;
        ay += v0.y + v1.y + v2.y + v3.y;
        az += v0.z + v1.z + v2.z + v3.z;
        aw += v0.w + v1.w + v2.w + v3.w;
    }
    for (; j < d; j++) {
        int s = lst[j];
        float4 v = *reinterpret_cast<const float4*>(&x[(size_t)s * FH + lane * 4]);
        ax += v.x; ay += v.y; az += v.z; aw += v.w;
    }
    *reinterpret_cast<float4*>(&agg[(size_t)node * FH + lane * 4]) =
        make_float4(ax, ay, az, aw);
}

// ---------------------------------------------------------------------------
// Fused GraphConv GEMM with packed f32x2 FFMA.
// out[n,h] = sum_f A[n,f]*Wa[h,f] + sum_f X[n,f]*Wb[h,f] + bias[h]
// Tile: 64 rows x 128 cols, 256 threads; thread computes 8 rows x 4 cols as
// 4 row-pairs x 4 cols packed accumulators.
// ---------------------------------------------------------------------------
__global__ void __launch_bounds__(256) k_gemm(
    const float* __restrict__ A, const float* __restrict__ X,
    const float* __restrict__ Wa, const float* __restrict__ Wb,
    const float* __restrict__ bias, float* __restrict__ out, int nrows) {
    __shared__ float sAT[32][72];    // [k][row] transposed; rows 0..63 used
    __shared__ float sW[32][132];    // [k][h]

    int row0 = blockIdx.x * 64;
    int tid = threadIdx.x;
    int tx = tid & 31;   // h = tx*4 .. tx*4+3
    int ty = tid >> 5;   // rows ty*8 .. ty*8+7

    unsigned long long acc2[4][4];   // [row-pair][col], each = (row 2rp, row 2rp+1)
#pragma unroll
    for (int i = 0; i < 4; i++)
#pragma unroll
        for (int j = 0; j < 4; j++) acc2[i][j] = 0ull;

    for (int kt = 0; kt < 8; kt++) {
        const float* Ap = (kt < 4) ? A : X;
        const float* Wp = (kt < 4) ? Wa : Wb;
        int f0 = (kt & 3) * 32;

        // Load A chunk transposed: sAT[kk][r] = Ap[row0+r][f0+kk]
#pragma unroll
        for (int i = 0; i < 2; i++) {
            int idx = tid * 2 + i;        // 0..511
            int r = idx >> 3;
            int c4 = idx & 7;
            float4 v = make_float4(0.f, 0.f, 0.f, 0.f);
            if (row0 + r < nrows)
                v = *reinterpret_cast<const float4*>(
                    &Ap[(size_t)(row0 + r) * FH + f0 + c4 * 4]);
            sAT[c4 * 4 + 0][r] = v.x;
            sAT[c4 * 4 + 1][r] = v.y;
            sAT[c4 * 4 + 2][r] = v.z;
            sAT[c4 * 4 + 3][r] = v.w;
        }
        // Load W chunk transposed: sW[k][h] = Wp[h][f0+k]
#pragma unroll
        for (int i = 0; i < 4; i++) {
            int idx = tid * 4 + i;        // 0..1023
            int h = idx >> 3;
            int c4 = idx & 7;
            float4 v = *reinterpret_cast<const float4*>(&Wp[h * FH + f0 + c4 * 4]);
            sW[c4 * 4 + 0][h] = v.x;
            sW[c4 * 4 + 1][h] = v.y;
            sW[c4 * 4 + 2][h] = v.z;
            sW[c4 * 4 + 3][h] = v.w;
        }
        __syncthreads();

#pragma unroll
        for (int k = 0; k < 32; k++) {
            float4 w = *reinterpret_cast<const float4*>(&sW[k][tx * 4]);
            unsigned long long wxx = pk2(w.x, w.x);
            unsigned long long wyy = pk2(w.y, w.y);
            unsigned long long wzz = pk2(w.z, w.z);
            unsigned long long www = pk2(w.w, w.w);
#pragma unroll
            for (int rp = 0; rp < 4; rp++) {
                // (a[2rp], a[2rp+1]) packed directly from transposed tile
                unsigned long long a2 = *reinterpret_cast<const unsigned long long*>(
                    &sAT[k][ty * 8 + rp * 2]);
                fma2(acc2[rp][0], a2, wxx);
                fma2(acc2[rp][1], a2, wyy);
                fma2(acc2[rp][2], a2, wzz);
                fma2(acc2[rp][3], a2, www);
            }
        }
        __syncthreads();
    }

    float4 b = *reinterpret_cast<const float4*>(&bias[tx * 4]);
#pragma unroll
    for (int rp = 0; rp < 4; rp++) {
        float lo[4], hi[4];
#pragma unroll
        for (int c = 0; c < 4; c++) unpk2(acc2[rp][c], lo[c], hi[c]);
        int r0 = row0 + ty * 8 + rp * 2;
        if (r0 < nrows) {
            float4 v = make_float4(lo[0] + b.x, lo[1] + b.y, lo[2] + b.z, lo[3] + b.w);
            *reinterpret_cast<float4*>(&out[(size_t)r0 * FH + tx * 4]) = v;
        }
        if (r0 + 1 < nrows) {
            float4 v = make_float4(hi[0] + b.x, hi[1] + b.y, hi[2] + b.z, hi[3] + b.w);
            *reinterpret_cast<float4*>(&out[(size_t)(r0 + 1) * FH + tx * 4]) = v;
        }
    }
}

// ---------------------------------------------------------------------------
__global__ void k_stats(const float* __restrict__ v, float* __restrict__ sum,
                        float* __restrict__ sq, int n) {
    int h = threadIdx.x;                 // 128
    int r0 = blockIdx.x * 128;
    int rend = min(r0 + 128, n);
    float s = 0.f, q = 0.f;
    for (int r = r0; r < rend; r++) {
        float x = fmaxf(v[(size_t)r * FH + h], 0.f);
        s += x;
        q += x * x;
    }
    atomicAdd(&sum[h], s);
    atomicAdd(&sq[h], q);
}

__global__ void k_bnparams(const float* __restrict__ sum, const float* __restrict__ sq,
                           const float* __restrict__ gamma, const float* __restrict__ beta,
                           float* __restrict__ scale, float* __restrict__ shift, float n) {
    int h = threadIdx.x;
    if (h < FH) {
        float invn = 1.0f / n;
        float m = sum[h] * invn;
        float var = sq[h] * invn - m * m;
        float s = gamma[h] * rsqrtf(var + BN_EPS);
        scale[h] = s;
        shift[h] = beta[h] - m * s;
    }
}

__global__ void k_apply_pool(const float* __restrict__ newv, const float* __restrict__ scale,
                             const float* __restrict__ shift, const int* __restrict__ batch,
                             const float* __restrict__ invcnt, float* __restrict__ xout,
                             float* __restrict__ pooled, int n) {
    int t = blockIdx.x * blockDim.x + threadIdx.x;
    if (t >= n * 32) return;
    int r = t >> 5;
    int lane = t & 31;
    int b = batch[r];
    float ic = invcnt[b];
    float4 x = *reinterpret_cast<const float4*>(&newv[(size_t)r * FH + lane * 4]);
    float4 sc = *reinterpret_cast<const float4*>(&scale[lane * 4]);
    float4 sh = *reinterpret_cast<const float4*>(&shift[lane * 4]);
    float4 y;
    y.x = fmaxf(x.x, 0.f) * sc.x + sh.x;
    y.y = fmaxf(x.y, 0.f) * sc.y + sh.y;
    y.z = fmaxf(x.z, 0.f) * sc.z + sh.z;
    y.w = fmaxf(x.w, 0.f) * sc.w + sh.w;
    *reinterpret_cast<float4*>(&xout[(size_t)r * FH + lane * 4]) = y;
    red_add_v4(&pooled[(size_t)b * FH + lane * 4],
               make_float4(y.x * ic, y.y * ic, y.z * ic, y.w * ic));
}

__global__ void k_logits(const float* __restrict__ feats, const float* __restrict__ fcW,
                         const float* __restrict__ fcb, float* __restrict__ out) {
    int lg = blockIdx.x;
    int l = lg / GC;
    __shared__ float sf[FH];
    sf[threadIdx.x] = feats[(size_t)lg * FH + threadIdx.x];
    __syncthreads();
    int c = threadIdx.x;
    if (c < CC) {
        const float* w = &fcW[(size_t)(l * CC + c) * FH];
        float a = fcb[l * CC + c];
#pragma unroll 8
        for (int h = 0; h < FH; h++) a += sf[h] * w[h];
        out[(size_t)lg * CC + c] = a;
    }
}

// ---------------------------------------------------------------------------
extern "C" void kernel_launch(void* const* d_in, const int* in_sizes, int n_in,
                              void* d_out, int out_size) {
    const float* x_user    = (const float*)d_in[0];
    const float* x_item    = (const float*)d_in[1];
    const int*   e_u2i     = (const int*)d_in[2];
    const int*   e_i2u     = (const int*)d_in[3];
    const int*   b_user    = (const int*)d_in[4];
    const int*   b_item    = (const int*)d_in[5];
    const float* Wrel_u2i  = (const float*)d_in[6];
    const float* Wroot_u2i = (const float*)d_in[7];
    const float* bias_u2i  = (const float*)d_in[8];
    const float* Wrel_i2u  = (const float*)d_in[9];
    const float* Wroot_i2u = (const float*)d_in[10];
    const float* bias_i2u  = (const float*)d_in[11];
    const float* bng_u     = (const float*)d_in[12];
    const float* bnb_u     = (const float*)d_in[13];
    const float* bng_i     = (const float*)d_in[14];
    const float* bnb_i     = (const float*)d_in[15];
    const float* fcW       = (const float*)d_in[16];
    const float* fcb       = (const float*)d_in[17];
    float* out = (float*)d_out;

    float* buf = nullptr;
    cudaGetSymbolAddress((void**)&buf, g_buf);
    int* deg = nullptr;
    cudaGetSymbolAddress((void**)&deg, g_deg);
    int* csr = nullptr;
    cudaGetSymbolAddress((void**)&csr, g_csr);

    int* deg_i = deg;                 // buckets keyed by item dst (u2i edges)
    int* deg_u = deg + 50000;         // buckets keyed by user dst (i2u edges)
    int* csr_i = csr;
    int* csr_u = csr + 50000ull * DEGCAP;

    float* cnt     = buf + OFF_CNT;
    float* inv     = buf + OFF_INV;
    float* sum_u   = buf + OFF_STATS;
    float* sq_u    = sum_u + FH;
    float* sum_i   = sq_u + FH;
    float* sq_i    = sum_i + FH;
    float* scale_u = buf + OFF_BN;
    float* shift_u = scale_u + FH;
    float* scale_i = shift_u + FH;
    float* shift_i = scale_i + FH;

    float* agg_u = buf + OFF_AGU;
    float* agg_i = buf + OFF_AGI;
    float* new_u = buf + OFF_NWU;
    float* new_i = buf + OFF_NWI;

    const int OUT_ELEMS = LC * GC * CC + LC * GC * FH;   // 221184
    float* feats = out + LC * GC * CC;

    // Zero output (feats accumulated with reds), counts, degree arrays
    k_zero<<<(OUT_ELEMS / 4 + 255) / 256, 256>>>(out, OUT_ELEMS / 4);
    k_zero<<<1, 256>>>(cnt, GC / 4);
    k_zero<<<(100000 / 4 + 255) / 256, 256>>>((float*)deg, 100000 / 4);
    k_count<<<(NU + NI + 255) / 256, 256>>>(b_user, b_item, cnt);
    k_invcnt<<<1, GC>>>(cnt, inv);

    // Build edge buckets once (reused across all 3 layers)
    k_build<<<(EC + 255) / 256, 256>>>(e_u2i, deg_i, csr_i);
    k_build<<<(EC + 255) / 256, 256>>>(e_i2u, deg_u, csr_u);

    const float* xu = x_user;
    const float* xi = x_item;

    for (int l = 0; l < LC; l++) {
        float* xu_n = buf + ((l & 1) ? OFF_XU1 : OFF_XU0);
        float* xi_n = buf + ((l & 1) ? OFF_XI1 : OFF_XI0);

        // Gather along both relations (writes every row; no zeroing needed)
        k_gather<<<(NI * 32 + 255) / 256, 256>>>(xu, deg_i, csr_i, agg_i);
        k_gather<<<(NU * 32 + 255) / 256, 256>>>(xi, deg_u, csr_u, agg_u);

        // Fused GraphConv GEMMs (packed f32x2)
        k_gemm<<<(NI + 63) / 64, 256>>>(agg_i, xi, Wrel_u2i + l * FH * FH,
                                        Wroot_u2i + l * FH * FH, bias_u2i + l * FH,
                                        new_i, NI);
        k_gemm<<<(NU + 63) / 64, 256>>>(agg_u, xu, Wrel_i2u + l * FH * FH,
                                        Wroot_i2u + l * FH * FH, bias_i2u + l * FH,
                                        new_u, NU);

        // BN statistics
        k_zero<<<1, 256>>>(sum_u, 512 / 4);
        k_stats<<<(NU + 127) / 128, 128>>>(new_u, sum_u, sq_u, NU);
        k_stats<<<(NI + 127) / 128, 128>>>(new_i, sum_i, sq_i, NI);
        k_bnparams<<<1, FH>>>(sum_u, sq_u, bng_u, bnb_u, scale_u, shift_u, (float)NU);
        k_bnparams<<<1, FH>>>(sum_i, sq_i, bng_i, bnb_i, scale_i, shift_i, (float)NI);

        // relu + BN apply, next features, group-mean pool accumulation
        float* fl = feats + (size_t)l * GC * FH;
        k_apply_pool<<<(NU * 32 + 255) / 256, 256>>>(new_u, scale_u, shift_u, b_user,
                                                     inv, xu_n, fl, NU);
        k_apply_pool<<<(NI * 32 + 255) / 256, 256>>>(new_i, scale_i, shift_i, b_item,
                                                     inv, xi_n, fl, NI);

        xu = xu_n;
        xi = xi_n;
    }

    k_logits<<<LC * GC, FH>>>(feats, fcW, fcb, out);
}

// round 4
// speedup vs baseline: 1.4115x; 1.0052x over previous
#include <cuda_runtime.h>
#include <cuda_bf16.h>
#include <cstdint>
#include <cstdio>

// Problem constants
#define NU 50000
#define NI 50000
#define FH 128
#define EC 800000
#define GC 512
#define CC 16
#define LC 3
#define BN_EPS 1e-5f
#define DEGCAP 96

// ---------------------------------------------------------------------------
// Scratch
// ---------------------------------------------------------------------------
#define NODEF (50000ull * 128ull)              // 6,400,000 floats
#define OFF_XU0 (0ull)
#define OFF_XU1 (1ull * NODEF)
#define OFF_XI0 (2ull * NODEF)
#define OFF_XI1 (3ull * NODEF)
#define OFF_AGU (4ull * NODEF)
#define OFF_AGI (5ull * NODEF)
#define OFF_NWU (6ull * NODEF)
#define OFF_NWI (7ull * NODEF)
#define OFF_CNT (8ull * NODEF)
#define OFF_INV (OFF_CNT + 512ull)
#define OFF_STATS (OFF_INV + 512ull)
#define OFF_BN (OFF_STATS + 512ull)
#define BUF_TOTAL (OFF_BN + 512ull)

__device__ float g_buf[BUF_TOTAL];
__device__ int g_deg[2 * 50000];               // [0..NU): item-dst? see usage
__device__ int g_csr[2ull * 50000ull * DEGCAP];

// ---------------------------------------------------------------------------
// f32x2 packed helpers (sm_10x)
// ---------------------------------------------------------------------------
__device__ __forceinline__ unsigned long long pk2(float lo, float hi) {
    unsigned long long r;
    asm("mov.b64 %0, {%1, %2};" : "=l"(r) : "f"(lo), "f"(hi));
    return r;
}
__device__ __forceinline__ void unpk2(unsigned long long v, float& lo, float& hi) {
    asm("mov.b64 {%0, %1}, %2;" : "=f"(lo), "=f"(hi) : "l"(v));
}
__device__ __forceinline__ void fma2(unsigned long long& d, unsigned long long a,
                                     unsigned long long b) {
    asm("fma.rn.f32x2 %0, %1, %2, %0;" : "+l"(d) : "l"(a), "l"(b));
}

__device__ __forceinline__ void red_add_v4(float* addr, float4 v) {
    asm volatile("red.global.add.v4.f32 [%0], {%1,%2,%3,%4};"
                 :: "l"(addr), "f"(v.x), "f"(v.y), "f"(v.z), "f"(v.w)
                 : "memory");
}

// ---------------------------------------------------------------------------
__global__ void k_zero(float* __restrict__ p, int n4) {
    int t = blockIdx.x * blockDim.x + threadIdx.x;
    if (t < n4) reinterpret_cast<float4*>(p)[t] = make_float4(0.f, 0.f, 0.f, 0.f);
}

__global__ void k_count(const int* __restrict__ bu, const int* __restrict__ bi,
                        float* __restrict__ cnt) {
    int t = blockIdx.x * blockDim.x + threadIdx.x;
    if (t < NU) {
        atomicAdd(&cnt[bu[t]], 1.0f);
    } else {
        int j = t - NU;
        if (j < NI) atomicAdd(&cnt[bi[j]], 1.0f);
    }
}

__global__ void k_invcnt(const float* __restrict__ cnt, float* __restrict__ inv) {
    int t = threadIdx.x;
    if (t < GC) inv[t] = 1.0f / fmaxf(cnt[t], 1.0f);
}

// ---------------------------------------------------------------------------
// CSR bucket build: for each edge, append src into dst's bucket.
// edge layout: [0..E) = src, [E..2E) = dst
// ---------------------------------------------------------------------------
__global__ void k_build(const int* __restrict__ edge, int* __restrict__ deg,
                        int* __restrict__ csr) {
    int e = blockIdx.x * blockDim.x + threadIdx.x;
    if (e >= EC) return;
    int src = edge[e];
    int dst = edge[EC + e];
    int pos = atomicAdd(&deg[dst], 1);
    if (pos < DEGCAP) csr[(size_t)dst * DEGCAP + pos] = src;
}

// ---------------------------------------------------------------------------
// Gather: agg[dst] = sum over bucket of x[src]. 32 lanes/node, float4/lane.
// Writes every row -> no pre-zero needed.
// ---------------------------------------------------------------------------
__global__ void k_gather(const float* __restrict__ x, const int* __restrict__ deg,
                         const int* __restrict__ csr, float* __restrict__ agg) {
    int t = blockIdx.x * blockDim.x + threadIdx.x;
    int node = t >> 5;
    int lane = t & 31;
    if (node >= 50000) return;
    int d = deg[node];
    if (d > DEGCAP) d = DEGCAP;
    const int* lst = csr + (size_t)node * DEGCAP;
    float ax = 0.f, ay = 0.f, az = 0.f, aw = 0.f;
    int j = 0;
    for (; j + 4 <= d; j += 4) {
        int s0 = lst[j], s1 = lst[j + 1], s2 = lst[j + 2], s3 = lst[j + 3];
        float4 v0 = *reinterpret_cast<const float4*>(&x[(size_t)s0 * FH + lane * 4]);
        float4 v1 = *reinterpret_cast<const float4*>(&x[(size_t)s1 * FH + lane * 4]);
        float4 v2 = *reinterpret_cast<const float4*>(&x[(size_t)s2 * FH + lane * 4]);
        float4 v3 = *reinterpret_cast<const float4*>(&x[(size_t)s3 * FH + lane * 4]);
        ax += v0.x + v1.x + v2.x + v3.x;
        ay += v0.y + v1.y + v2.y + v3.y;
        az += v0.z + v1.z + v2.z + v3.z;
        aw += v0.w + v1.w + v2.w + v3.w;
    }
    for (; j < d; j++) {
        int s = lst[j];
        float4 v = *reinterpret_cast<const float4*>(&x[(size_t)s * FH + lane * 4]);
        ax += v.x; ay += v.y; az += v.z; aw += v.w;
    }
    *reinterpret_cast<float4*>(&agg[(size_t)node * FH + lane * 4]) =
        make_float4(ax, ay, az, aw);
}

// ---------------------------------------------------------------------------
// Fused GraphConv GEMM with packed f32x2 FFMA.
// out[n,h] = sum_f A[n,f]*Wa[h,f] + sum_f X[n,f]*Wb[h,f] + bias[h]
// Tile: 64 rows x 128 cols, 256 threads; thread computes 8 rows x 4 cols as
// 4 row-pairs x 4 cols packed accumulators.
// ---------------------------------------------------------------------------
__global__ void __launch_bounds__(256) k_gemm(
    const float* __restrict__ A, const float* __restrict__ X,
    const float* __restrict__ Wa, const float* __restrict__ Wb,
    const float* __restrict__ bias, float* __restrict__ out, int nrows) {
    __shared__ float sAT[32][72];    // [k][row] transposed; rows 0..63 used
    __shared__ float sW[32][132];    // [k][h]

    int row0 = blockIdx.x * 64;
    int tid = threadIdx.x;
    int tx = tid & 31;   // h = tx*4 .. tx*4+3
    int ty = tid >> 5;   // rows ty*8 .. ty*8+7

    unsigned long long acc2[4][4];   // [row-pair][col], each = (row 2rp, row 2rp+1)
#pragma unroll
    for (int i = 0; i < 4; i++)
#pragma unroll
        for (int j = 0; j < 4; j++) acc2[i][j] = 0ull;

    for (int kt = 0; kt < 8; kt++) {
        const float* Ap = (kt < 4) ? A : X;
        const float* Wp = (kt < 4) ? Wa : Wb;
        int f0 = (kt & 3) * 32;

        // Load A chunk transposed: sAT[kk][r] = Ap[row0+r][f0+kk]
#pragma unroll
        for (int i = 0; i < 2; i++) {
            int idx = tid * 2 + i;        // 0..511
            int r = idx >> 3;
            int c4 = idx & 7;
            float4 v = make_float4(0.f, 0.f, 0.f, 0.f);
            if (row0 + r < nrows)
                v = *reinterpret_cast<const float4*>(
                    &Ap[(size_t)(row0 + r) * FH + f0 + c4 * 4]);
            sAT[c4 * 4 + 0][r] = v.x;
            sAT[c4 * 4 + 1][r] = v.y;
            sAT[c4 * 4 + 2][r] = v.z;
            sAT[c4 * 4 + 3][r] = v.w;
        }
        // Load W chunk transposed: sW[k][h] = Wp[h][f0+k]
#pragma unroll
        for (int i = 0; i < 4; i++) {
            int idx = tid * 4 + i;        // 0..1023
            int h = idx >> 3;
            int c4 = idx & 7;
            float4 v = *reinterpret_cast<const float4*>(&Wp[h * FH + f0 + c4 * 4]);
            sW[c4 * 4 + 0][h] = v.x;
            sW[c4 * 4 + 1][h] = v.y;
            sW[c4 * 4 + 2][h] = v.z;
            sW[c4 * 4 + 3][h] = v.w;
        }
        __syncthreads();

#pragma unroll
        for (int k = 0; k < 32; k++) {
            float4 w = *reinterpret_cast<const float4*>(&sW[k][tx * 4]);
            unsigned long long wxx = pk2(w.x, w.x);
            unsigned long long wyy = pk2(w.y, w.y);
            unsigned long long wzz = pk2(w.z, w.z);
            unsigned long long www = pk2(w.w, w.w);
#pragma unroll
            for (int rp = 0; rp < 4; rp++) {
                // (a[2rp], a[2rp+1]) packed directly from transposed tile
                unsigned long long a2 = *reinterpret_cast<const unsigned long long*>(
                    &sAT[k][ty * 8 + rp * 2]);
                fma2(acc2[rp][0], a2, wxx);
                fma2(acc2[rp][1], a2, wyy);
                fma2(acc2[rp][2], a2, wzz);
                fma2(acc2[rp][3], a2, www);
            }
        }
        __syncthreads();
    }

    float4 b = *reinterpret_cast<const float4*>(&bias[tx * 4]);
#pragma unroll
    for (int rp = 0; rp < 4; rp++) {
        float lo[4], hi[4];
#pragma unroll
        for (int c = 0; c < 4; c++) unpk2(acc2[rp][c], lo[c], hi[c]);
        int r0 = row0 + ty * 8 + rp * 2;
        if (r0 < nrows) {
            float4 v = make_float4(lo[0] + b.x, lo[1] + b.y, lo[2] + b.z, lo[3] + b.w);
            *reinterpret_cast<float4*>(&out[(size_t)r0 * FH + tx * 4]) = v;
        }
        if (r0 + 1 < nrows) {
            float4 v = make_float4(hi[0] + b.x, hi[1] + b.y, hi[2] + b.z, hi[3] + b.w);
            *reinterpret_cast<float4*>(&out[(size_t)(r0 + 1) * FH + tx * 4]) = v;
        }
    }
}

// ---------------------------------------------------------------------------
__global__ void k_stats(const float* __restrict__ v, float* __restrict__ sum,
                        float* __restrict__ sq, int n) {
    int h = threadIdx.x;                 // 128
    int r0 = blockIdx.x * 128;
    int rend = min(r0 + 128, n);
    float s = 0.f, q = 0.f;
    for (int r = r0; r < rend; r++) {
        float x = fmaxf(v[(size_t)r * FH + h], 0.f);
        s += x;
        q += x * x;
    }
    atomicAdd(&sum[h], s);
    atomicAdd(&sq[h], q);
}

__global__ void k_bnparams(const float* __restrict__ sum, const float* __restrict__ sq,
                           const float* __restrict__ gamma, const float* __restrict__ beta,
                           float* __restrict__ scale, float* __restrict__ shift, float n) {
    int h = threadIdx.x;
    if (h < FH) {
        float invn = 1.0f / n;
        float m = sum[h] * invn;
        float var = sq[h] * invn - m * m;
        float s = gamma[h] * rsqrtf(var + BN_EPS);
        scale[h] = s;
        shift[h] = beta[h] - m * s;
    }
}

__global__ void k_apply_pool(const float* __restrict__ newv, const float* __restrict__ scale,
                             const float* __restrict__ shift, const int* __restrict__ batch,
                             const float* __restrict__ invcnt, float* __restrict__ xout,
                             float* __restrict__ pooled, int n) {
    int t = blockIdx.x * blockDim.x + threadIdx.x;
    if (t >= n * 32) return;
    int r = t >> 5;
    int lane = t & 31;
    int b = batch[r];
    float ic = invcnt[b];
    float4 x = *reinterpret_cast<const float4*>(&newv[(size_t)r * FH + lane * 4]);
    float4 sc = *reinterpret_cast<const float4*>(&scale[lane * 4]);
    float4 sh = *reinterpret_cast<const float4*>(&shift[lane * 4]);
    float4 y;
    y.x = fmaxf(x.x, 0.f) * sc.x + sh.x;
    y.y = fmaxf(x.y, 0.f) * sc.y + sh.y;
    y.z = fmaxf(x.z, 0.f) * sc.z + sh.z;
    y.w = fmaxf(x.w, 0.f) * sc.w + sh.w;
    *reinterpret_cast<float4*>(&xout[(size_t)r * FH + lane * 4]) = y;
    red_add_v4(&pooled[(size_t)b * FH + lane * 4],
               make_float4(y.x * ic, y.y * ic, y.z * ic, y.w * ic));
}

__global__ void k_logits(const float* __restrict__ feats, const float* __restrict__ fcW,
                         const float* __restrict__ fcb, float* __restrict__ out) {
    int lg = blockIdx.x;
    int l = lg / GC;
    __shared__ float sf[FH];
    sf[threadIdx.x] = feats[(size_t)lg * FH + threadIdx.x];
    __syncthreads();
    int c = threadIdx.x;
    if (c < CC) {
        const float* w = &fcW[(size_t)(l * CC + c) * FH];
        float a = fcb[l * CC + c];
#pragma unroll 8
        for (int h = 0; h < FH; h++) a += sf[h] * w[h];
        out[(size_t)lg * CC + c] = a;
    }
}

// ---------------------------------------------------------------------------
extern "C" void kernel_launch(void* const* d_in, const int* in_sizes, int n_in,
                              void* d_out, int out_size) {
    const float* x_user    = (const float*)d_in[0];
    const float* x_item    = (const float*)d_in[1];
    const int*   e_u2i     = (const int*)d_in[2];
    const int*   e_i2u     = (const int*)d_in[3];
    const int*   b_user    = (const int*)d_in[4];
    const int*   b_item    = (const int*)d_in[5];
    const float* Wrel_u2i  = (const float*)d_in[6];
    const float* Wroot_u2i = (const float*)d_in[7];
    const float* bias_u2i  = (const float*)d_in[8];
    const float* Wrel_i2u  = (const float*)d_in[9];
    const float* Wroot_i2u = (const float*)d_in[10];
    const float* bias_i2u  = (const float*)d_in[11];
    const float* bng_u     = (const float*)d_in[12];
    const float* bnb_u     = (const float*)d_in[13];
    const float* bng_i     = (const float*)d_in[14];
    const float* bnb_i     = (const float*)d_in[15];
    const float* fcW       = (const float*)d_in[16];
    const float* fcb       = (const float*)d_in[17];
    float* out = (float*)d_out;

    float* buf = nullptr;
    cudaGetSymbolAddress((void**)&buf, g_buf);
    int* deg = nullptr;
    cudaGetSymbolAddress((void**)&deg, g_deg);
    int* csr = nullptr;
    cudaGetSymbolAddress((void**)&csr, g_csr);

    int* deg_i = deg;                 // buckets keyed by item dst (u2i edges)
    int* deg_u = deg + 50000;         // buckets keyed by user dst (i2u edges)
    int* csr_i = csr;
    int* csr_u = csr + 50000ull * DEGCAP;

    float* cnt     = buf + OFF_CNT;
    float* inv     = buf + OFF_INV;
    float* sum_u   = buf + OFF_STATS;
    float* sq_u    = sum_u + FH;
    float* sum_i   = sq_u + FH;
    float* sq_i    = sum_i + FH;
    float* scale_u = buf + OFF_BN;
    float* shift_u = scale_u + FH;
    float* scale_i = shift_u + FH;
    float* shift_i = scale_i + FH;

    float* agg_u = buf + OFF_AGU;
    float* agg_i = buf + OFF_AGI;
    float* new_u = buf + OFF_NWU;
    float* new_i = buf + OFF_NWI;

    const int OUT_ELEMS = LC * GC * CC + LC * GC * FH;   // 221184
    float* feats = out + LC * GC * CC;

    // Zero output (feats accumulated with reds), counts, degree arrays
    k_zero<<<(OUT_ELEMS / 4 + 255) / 256, 256>>>(out, OUT_ELEMS / 4);
    k_zero<<<1, 256>>>(cnt, GC / 4);
    k_zero<<<(100000 / 4 + 255) / 256, 256>>>((float*)deg, 100000 / 4);
    k_count<<<(NU + NI + 255) / 256, 256>>>(b_user, b_item, cnt);
    k_invcnt<<<1, GC>>>(cnt, inv);

    // Build edge buckets once (reused across all 3 layers)
    k_build<<<(EC + 255) / 256, 256>>>(e_u2i, deg_i, csr_i);
    k_build<<<(EC + 255) / 256, 256>>>(e_i2u, deg_u, csr_u);

    const float* xu = x_user;
    const float* xi = x_item;

    for (int l = 0; l < LC; l++) {
        float* xu_n = buf + ((l & 1) ? OFF_XU1 : OFF_XU0);
        float* xi_n = buf + ((l & 1) ? OFF_XI1 : OFF_XI0);

        // Gather along both relations (writes every row; no zeroing needed)
        k_gather<<<(NI * 32 + 255) / 256, 256>>>(xu, deg_i, csr_i, agg_i);
        k_gather<<<(NU * 32 + 255) / 256, 256>>>(xi, deg_u, csr_u, agg_u);

        // Fused GraphConv GEMMs (packed f32x2)
        k_gemm<<<(NI + 63) / 64, 256>>>(agg_i, xi, Wrel_u2i + l * FH * FH,
                                        Wroot_u2i + l * FH * FH, bias_u2i + l * FH,
                                        new_i, NI);
        k_gemm<<<(NU + 63) / 64, 256>>>(agg_u, xu, Wrel_i2u + l * FH * FH,
                                        Wroot_i2u + l * FH * FH, bias_i2u + l * FH,
                                        new_u, NU);

        // BN statistics
        k_zero<<<1, 256>>>(sum_u, 512 / 4);
        k_stats<<<(NU + 127) / 128, 128>>>(new_u, sum_u, sq_u, NU);
        k_stats<<<(NI + 127) / 128, 128>>>(new_i, sum_i, sq_i, NI);
        k_bnparams<<<1, FH>>>(sum_u, sq_u, bng_u, bnb_u, scale_u, shift_u, (float)NU);
        k_bnparams<<<1, FH>>>(sum_i, sq_i, bng_i, bnb_i, scale_i, shift_i, (float)NI);

        // relu + BN apply, next features, group-mean pool accumulation
        float* fl = feats + (size_t)l * GC * FH;
        k_apply_pool<<<(NU * 32 + 255) / 256, 256>>>(new_u, scale_u, shift_u, b_user,
                                                     inv, xu_n, fl, NU);
        k_apply_pool<<<(NI * 32 + 255) / 256, 256>>>(new_i, scale_i, shift_i, b_item,
                                                     inv, xi_n, fl, NI);

        xu = xu_n;
        xi = xi_n;
    }

    k_logits<<<LC * GC, FH>>>(feats, fcW, fcb, out);
}

// round 6
// speedup vs baseline: 2.3807x; 1.6866x over previous
#include <cuda_runtime.h>
#include <cstdint>

#define NU 50000
#define NI 50000
#define FH 128
#define EC 800000
#define GC 512
#define CC 16
#define LC 3
#define BN_EPS 1e-5f
#define DEGCAP 96
#define NT 391

#define NODEF (50000ull * 128ull)
#define OFF_XU 0ull
#define OFF_XI (1ull * NODEF)
#define OFF_AGU (2ull * NODEF)
#define OFF_AGI (3ull * NODEF)
#define OFF_NWU (4ull * NODEF)
#define OFF_NWI (5ull * NODEF)
#define OFF_CNT (6ull * NODEF)
#define OFF_INV (OFF_CNT + 512ull)
#define OFF_STATS (OFF_INV + 512ull)
#define OFF_BN (OFF_STATS + 512ull)
#define BUF_TOTAL (OFF_BN + 512ull)

__device__ float g_buf[BUF_TOTAL];
__device__ int g_deg[2 * 50000];
__device__ int g_csr[2ull * 50000ull * DEGCAP];

// ---------------- helpers ----------------
__device__ __forceinline__ float to_tf32(float x) {
    uint32_t r;
    asm("cvt.rn.tf32.f32 %0, %1;" : "=r"(r) : "f"(x));
    return __uint_as_float(r);
}
__device__ __forceinline__ void red_add_v4(float* a, float4 v) {
    asm volatile("red.global.add.v4.f32 [%0], {%1,%2,%3,%4};"
                 :: "l"(a), "f"(v.x), "f"(v.y), "f"(v.z), "f"(v.w) : "memory");
}
__device__ __forceinline__ void mma_tf32(float* c, const uint32_t* a,
                                         uint32_t b0, uint32_t b1) {
    asm volatile(
        "mma.sync.aligned.m16n8k8.row.col.f32.tf32.tf32.f32 "
        "{%0,%1,%2,%3}, {%4,%5,%6,%7}, {%8,%9}, {%0,%1,%2,%3};"
        : "+f"(c[0]), "+f"(c[1]), "+f"(c[2]), "+f"(c[3])
        : "r"(a[0]), "r"(a[1]), "r"(a[2]), "r"(a[3]), "r"(b0), "r"(b1));
}

// ---------------- simple kernels ----------------
__global__ void k_zero(float* __restrict__ p, int n4) {
    int t = blockIdx.x * blockDim.x + threadIdx.x;
    if (t < n4) reinterpret_cast<float4*>(p)[t] = make_float4(0.f, 0.f, 0.f, 0.f);
}

__global__ void k_count(const int* __restrict__ bu, const int* __restrict__ bi,
                        float* __restrict__ cnt) {
    int t = blockIdx.x * blockDim.x + threadIdx.x;
    if (t < NU) atomicAdd(&cnt[bu[t]], 1.0f);
    else if (t - NU < NI) atomicAdd(&cnt[bi[t - NU]], 1.0f);
}

__global__ void k_invcnt(const float* __restrict__ cnt, float* __restrict__ inv) {
    int t = threadIdx.x;
    if (t < GC) inv[t] = 1.0f / fmaxf(cnt[t], 1.0f);
}

__global__ void k_build(const int* __restrict__ edge, int* __restrict__ deg,
                        int* __restrict__ csr) {
    int e = blockIdx.x * blockDim.x + threadIdx.x;
    if (e >= EC) return;
    int src = edge[e];
    int dst = edge[EC + e];
    int pos = atomicAdd(&deg[dst], 1);
    if (pos < DEGCAP) csr[(size_t)dst * DEGCAP + pos] = src;
}

// merged gather (both relations); block 0 also zeroes BN stats for this layer
__global__ void k_gather(const float* __restrict__ xu, const float* __restrict__ xi,
                         float* __restrict__ aggU, float* __restrict__ aggI,
                         float* __restrict__ stats) {
    if (blockIdx.x == 0 && threadIdx.x < 128) {
#pragma unroll
        for (int i = 0; i < 4; i++) stats[threadIdx.x + i * 128] = 0.f;
    }
    int t = blockIdx.x * blockDim.x + threadIdx.x;
    int gn = t >> 5, lane = t & 31;
    if (gn >= 100000) return;
    const float* x;
    float* dst;
    const int* dp;
    const int* lst;
    int node;
    if (gn < 50000) {
        node = gn; x = xu; dst = aggI; dp = g_deg;
        lst = g_csr + (size_t)node * DEGCAP;
    } else {
        node = gn - 50000; x = xi; dst = aggU; dp = g_deg + 50000;
        lst = g_csr + 50000ull * DEGCAP + (size_t)node * DEGCAP;
    }
    int d = min(dp[node], DEGCAP);
    float ax = 0.f, ay = 0.f, az = 0.f, aw = 0.f;
    int j = 0;
    for (; j + 4 <= d; j += 4) {
        int s0 = lst[j], s1 = lst[j + 1], s2 = lst[j + 2], s3 = lst[j + 3];
        float4 v0 = *reinterpret_cast<const float4*>(&x[(size_t)s0 * FH + lane * 4]);
        float4 v1 = *reinterpret_cast<const float4*>(&x[(size_t)s1 * FH + lane * 4]);
        float4 v2 = *reinterpret_cast<const float4*>(&x[(size_t)s2 * FH + lane * 4]);
        float4 v3 = *reinterpret_cast<const float4*>(&x[(size_t)s3 * FH + lane * 4]);
        ax += v0.x + v1.x + v2.x + v3.x;
        ay += v0.y + v1.y + v2.y + v3.y;
        az += v0.z + v1.z + v2.z + v3.z;
        aw += v0.w + v1.w + v2.w + v3.w;
    }
    for (; j < d; j++) {
        int s = lst[j];
        float4 v = *reinterpret_cast<const float4*>(&x[(size_t)s * FH + lane * 4]);
        ax += v.x; ay += v.y; az += v.z; aw += v.w;
    }
    *reinterpret_cast<float4*>(&dst[(size_t)node * FH + lane * 4]) =
        make_float4(ax, ay, az, aw);
}

// ---------------- mma.sync tf32 GEMM ----------------
// out[n,h] = sum_f A0[n,f]*Wa[h,f] + sum_f A1[n,f]*Wb[h,f] + bias[h]
// CTA: 128 rows x 128 cols, K = 256 (8 chunks of 32). 8 warps: wm=wid&3 (M),
// wn=wid>>2 (N). Warp tile 32x64 = 2 x 8 m16n8k8 fragments. ldk=36 padding
// makes all fragment LDS conflict-free (bank = 4g+q+c mod 32, distinct).
__global__ void __launch_bounds__(256) k_gemm_mma(
    const float* __restrict__ aggI, const float* __restrict__ xI,
    const float* __restrict__ aggU, const float* __restrict__ xU,
    const float* __restrict__ WaI, const float* __restrict__ WbI,
    const float* __restrict__ WaU, const float* __restrict__ WbU,
    const float* __restrict__ bI, const float* __restrict__ bU,
    float* __restrict__ nI, float* __restrict__ nU) {
    __shared__ float sA[128 * 36];
    __shared__ float sW[128 * 36];

    int tid = threadIdx.x, wid = tid >> 5, lane = tid & 31;
    bool item = blockIdx.x < NT;
    int tile = item ? blockIdx.x : blockIdx.x - NT;
    const float* A0 = item ? aggI : aggU;
    const float* A1 = item ? xI : xU;
    const float* Wa = item ? WaI : WaU;
    const float* Wb = item ? WbI : WbU;
    const float* bias = item ? bI : bU;
    float* outp = item ? nI : nU;
    int row0 = tile * 128;

    int g = lane >> 2, q = lane & 3;
    int wm = wid & 3, wn = wid >> 2;

    float c[2][8][4];
#pragma unroll
    for (int mt = 0; mt < 2; mt++)
#pragma unroll
        for (int nt = 0; nt < 8; nt++)
#pragma unroll
            for (int e = 0; e < 4; e++) c[mt][nt][e] = 0.f;

#pragma unroll 1
    for (int ch = 0; ch < 8; ch++) {
        const float* Ap = (ch < 4) ? A0 : A1;
        const float* Wp = (ch < 4) ? Wa : Wb;
        int f0 = (ch & 3) * 32;

        __syncthreads();          // protect previous-iteration reads
        // stage A chunk (128x32, tf32-rounded), 4 float4/thread
#pragma unroll
        for (int i = 0; i < 4; i++) {
            int idx = i * 256 + tid;
            int r = idx >> 3, j = idx & 7;
            float4 v = make_float4(0.f, 0.f, 0.f, 0.f);
            if (row0 + r < 50000)
                v = *reinterpret_cast<const float4*>(
                    &Ap[(size_t)(row0 + r) * FH + f0 + j * 4]);
            v.x = to_tf32(v.x); v.y = to_tf32(v.y);
            v.z = to_tf32(v.z); v.w = to_tf32(v.w);
            *reinterpret_cast<float4*>(&sA[r * 36 + j * 4]) = v;
        }
        // stage W chunk (128x32, tf32-rounded)
#pragma unroll
        for (int i = 0; i < 4; i++) {
            int idx = i * 256 + tid;
            int r = idx >> 3, j = idx & 7;
            float4 v = *reinterpret_cast<const float4*>(&Wp[r * FH + f0 + j * 4]);
            v.x = to_tf32(v.x); v.y = to_tf32(v.y);
            v.z = to_tf32(v.z); v.w = to_tf32(v.w);
            *reinterpret_cast<float4*>(&sW[r * 36 + j * 4]) = v;
        }
        __syncthreads();

#pragma unroll
        for (int s = 0; s < 4; s++) {
            int k0 = s * 8;
            uint32_t a[2][4];
#pragma unroll
            for (int mt = 0; mt < 2; mt++) {
                int m0 = wm * 32 + mt * 16;
                a[mt][0] = __float_as_uint(sA[(m0 + g) * 36 + k0 + q]);
                a[mt][1] = __float_as_uint(sA[(m0 + g + 8) * 36 + k0 + q]);
                a[mt][2] = __float_as_uint(sA[(m0 + g) * 36 + k0 + q + 4]);
                a[mt][3] = __float_as_uint(sA[(m0 + g + 8) * 36 + k0 + q + 4]);
            }
#pragma unroll
            for (int nt = 0; nt < 8; nt++) {
                int n0 = wn * 64 + nt * 8;
                uint32_t b0 = __float_as_uint(sW[(n0 + g) * 36 + k0 + q]);
                uint32_t b1 = __float_as_uint(sW[(n0 + g) * 36 + k0 + q + 4]);
                mma_tf32(c[0][nt], a[0], b0, b1);
                mma_tf32(c[1][nt], a[1], b0, b1);
            }
        }
    }

    // epilogue: c[mt][nt] rows = row0+wm*32+mt*16+{g, g+8}, cols = n0+2q, +1
#pragma unroll
    for (int nt = 0; nt < 8; nt++) {
        int n0 = wn * 64 + nt * 8 + 2 * q;
        float2 bb = *reinterpret_cast<const float2*>(&bias[n0]);
#pragma unroll
        for (int mt = 0; mt < 2; mt++) {
            int r = row0 + wm * 32 + mt * 16 + g;
            if (r < 50000) {
                float2 o = make_float2(c[mt][nt][0] + bb.x, c[mt][nt][1] + bb.y);
                *reinterpret_cast<float2*>(&outp[(size_t)r * FH + n0]) = o;
            }
            if (r + 8 < 50000) {
                float2 o = make_float2(c[mt][nt][2] + bb.x, c[mt][nt][3] + bb.y);
                *reinterpret_cast<float2*>(&outp[(size_t)(r + 8) * FH + n0]) = o;
            }
        }
    }
}

// ---------------- BN / apply / logits ----------------
__global__ void k_stats(const float* __restrict__ nu_, const float* __restrict__ ni_,
                        float* __restrict__ stats) {
    int b = blockIdx.x;
    const float* v;
    float* s;
    int r0;
    if (b < NT) { v = nu_; s = stats; r0 = b * 128; }
    else { v = ni_; s = stats + 256; r0 = (b - NT) * 128; }
    int h = threadIdx.x;
    int re = min(r0 + 128, 50000);
    float a = 0.f, qq = 0.f;
    for (int r = r0; r < re; r++) {
        float x = fmaxf(v[(size_t)r * FH + h], 0.f);
        a += x;
        qq += x * x;
    }
    atomicAdd(&s[h], a);
    atomicAdd(&s[h + 128], qq);
}

__global__ void k_bnparams(const float* __restrict__ stats,
                           const float* __restrict__ gu, const float* __restrict__ bu,
                           const float* __restrict__ gi, const float* __restrict__ bi,
                           float* __restrict__ bn) {
    int t = threadIdx.x;
    int h = t & 127;
    const float* s = (t < 128) ? stats : stats + 256;
    const float* g = (t < 128) ? gu : gi;
    const float* be = (t < 128) ? bu : bi;
    float* o = (t < 128) ? bn : bn + 256;
    float invn = 1.0f / 50000.0f;
    float m = s[h] * invn;
    float var = s[h + 128] * invn - m * m;
    float sc = g[h] * rsqrtf(var + BN_EPS);
    o[h] = sc;
    o[h + 128] = be[h] - m * sc;
}

__global__ void k_apply(const float* __restrict__ nu_, const float* __restrict__ ni_,
                        const float* __restrict__ bn, const int* __restrict__ bu,
                        const int* __restrict__ bi, const float* __restrict__ inv,
                        float* __restrict__ XU, float* __restrict__ XI,
                        float* __restrict__ pooled) {
    int t = blockIdx.x * blockDim.x + threadIdx.x;
    if (t >= (NU + NI) * 32) return;
    int gn = t >> 5, lane = t & 31;
    const float* v;
    const float* sc;
    const int* bt;
    float* xo;
    int r;
    if (gn < NU) { v = nu_; sc = bn; bt = bu; xo = XU; r = gn; }
    else { v = ni_; sc = bn + 256; bt = bi; xo = XI; r = gn - NU; }
    int g = bt[r];
    float ic = inv[g];
    float4 x = *reinterpret_cast<const float4*>(&v[(size_t)r * FH + lane * 4]);
    float4 s4 = *reinterpret_cast<const float4*>(&sc[lane * 4]);
    float4 h4 = *reinterpret_cast<const float4*>(&sc[128 + lane * 4]);
    float4 y;
    y.x = fmaxf(x.x, 0.f) * s4.x + h4.x;
    y.y = fmaxf(x.y, 0.f) * s4.y + h4.y;
    y.z = fmaxf(x.z, 0.f) * s4.z + h4.z;
    y.w = fmaxf(x.w, 0.f) * s4.w + h4.w;
    *reinterpret_cast<float4*>(&xo[(size_t)r * FH + lane * 4]) = y;
    red_add_v4(&pooled[(size_t)g * FH + lane * 4],
               make_float4(y.x * ic, y.y * ic, y.z * ic, y.w * ic));
}

__global__ void k_logits(const float* __restrict__ feats, const float* __restrict__ fcW,
                         const float* __restrict__ fcb, float* __restrict__ out) {
    int lg = blockIdx.x;
    int l = lg / GC;
    __shared__ float sf[FH];
    sf[threadIdx.x] = feats[(size_t)lg * FH + threadIdx.x];
    __syncthreads();
    int c = threadIdx.x;
    if (c < CC) {
        const float* w = &fcW[(size_t)(l * CC + c) * FH];
        float a = fcb[l * CC + c];
#pragma unroll 8
        for (int h = 0; h < FH; h++) a += sf[h] * w[h];
        out[(size_t)lg * CC + c] = a;
    }
}

// ---------------------------------------------------------------------------
extern "C" void kernel_launch(void* const* d_in, const int* in_sizes, int n_in,
                              void* d_out, int out_size) {
    const float* x_user    = (const float*)d_in[0];
    const float* x_item    = (const float*)d_in[1];
    const int*   e_u2i     = (const int*)d_in[2];
    const int*   e_i2u     = (const int*)d_in[3];
    const int*   b_user    = (const int*)d_in[4];
    const int*   b_item    = (const int*)d_in[5];
    const float* Wrel_u2i  = (const float*)d_in[6];
    const float* Wroot_u2i = (const float*)d_in[7];
    const float* bias_u2i  = (const float*)d_in[8];
    const float* Wrel_i2u  = (const float*)d_in[9];
    const float* Wroot_i2u = (const float*)d_in[10];
    const float* bias_i2u  = (const float*)d_in[11];
    const float* bng_u     = (const float*)d_in[12];
    const float* bnb_u     = (const float*)d_in[13];
    const float* bng_i     = (const float*)d_in[14];
    const float* bnb_i     = (const float*)d_in[15];
    const float* fcW       = (const float*)d_in[16];
    const float* fcb       = (const float*)d_in[17];
    float* out = (float*)d_out;

    float* buf = nullptr;
    cudaGetSymbolAddress((void**)&buf, g_buf);
    int* deg = nullptr;
    cudaGetSymbolAddress((void**)&deg, g_deg);
    int* csr = nullptr;
    cudaGetSymbolAddress((void**)&csr, g_csr);

    float* XU    = buf + OFF_XU;
    float* XI    = buf + OFF_XI;
    float* agg_u = buf + OFF_AGU;
    float* agg_i = buf + OFF_AGI;
    float* new_u = buf + OFF_NWU;
    float* new_i = buf + OFF_NWI;
    float* cnt   = buf + OFF_CNT;
    float* inv   = buf + OFF_INV;
    float* stats = buf + OFF_STATS;
    float* bn    = buf + OFF_BN;

    const int OUT_ELEMS = LC * GC * CC + LC * GC * FH;
    float* feats = out + LC * GC * CC;

    int* csr_u = csr + 50000ull * DEGCAP;

    k_zero<<<(100000 / 4 + 255) / 256, 256>>>((float*)deg, 100000 / 4);        // 0
    k_build<<<(EC + 255) / 256, 256>>>(e_u2i, deg, csr);                        // 1
    k_build<<<(EC + 255) / 256, 256>>>(e_i2u, deg + 50000, csr_u);              // 2
    k_gather<<<(100000 * 32 + 255) / 256, 256>>>(x_user, x_item, agg_u, agg_i,
                                                 stats);                        // 3 (ncu)
    k_zero<<<(OUT_ELEMS / 4 + 255) / 256, 256>>>(out, OUT_ELEMS / 4);           // 4
    k_zero<<<1, 128>>>(cnt, GC / 4);                                            // 5
    k_count<<<(NU + NI + 255) / 256, 256>>>(b_user, b_item, cnt);               // 6
    k_invcnt<<<1, GC>>>(cnt, inv);                                              // 7

    const float* xu = x_user;
    const float* xi = x_item;

    for (int l = 0; l < LC; l++) {
        if (l > 0)
            k_gather<<<(100000 * 32 + 255) / 256, 256>>>(xu, xi, agg_u, agg_i, stats);
        size_t wo = (size_t)l * FH * FH;
        k_gemm_mma<<<2 * NT, 256>>>(agg_i, xi, agg_u, xu,
                                    Wrel_u2i + wo, Wroot_u2i + wo,
                                    Wrel_i2u + wo, Wroot_i2u + wo,
                                    bias_u2i + l * FH, bias_i2u + l * FH,
                                    new_i, new_u);
        k_stats<<<2 * NT, 128>>>(new_u, new_i, stats);
        k_bnparams<<<1, 256>>>(stats, bng_u, bnb_u, bng_i, bnb_i, bn);
        float* fl = feats + (size_t)l * GC * FH;
        k_apply<<<((NU + NI) * 32 + 255) / 256, 256>>>(new_u, new_i, bn, b_user,
                                                       b_item, inv, XU, XI, fl);
        xu = XU;
        xi = XI;
    }

    k_logits<<<LC * GC, FH>>>(feats, fcW, fcb, out);
}

// round 8
// speedup vs baseline: 2.5333x; 1.0641x over previous
#include <cuda_runtime.h>
#include <cstdint>

#define NU 50000
#define NI 50000
#define FH 128
#define EC 800000
#define GC 512
#define CC 16
#define LC 3
#define BN_EPS 1e-5f
#define DEGCAP 96
#define NT 391

#define NODEF (50000ull * 128ull)
#define OFF_XU 0ull
#define OFF_XI (1ull * NODEF)
#define OFF_AGU (2ull * NODEF)
#define OFF_AGI (3ull * NODEF)
#define OFF_NWU (4ull * NODEF)
#define OFF_NWI (5ull * NODEF)
#define OFF_CNT (6ull * NODEF)
#define OFF_INV (OFF_CNT + 512ull)
#define OFF_STATS (OFF_INV + 512ull)
#define OFF_BN (OFF_STATS + 512ull)
#define BUF_TOTAL (OFF_BN + 512ull)

__device__ float g_buf[BUF_TOTAL];
__device__ int g_deg[2 * 50000];
__device__ int g_csr[2ull * 50000ull * DEGCAP];
__device__ unsigned g_ctr_stats;   // zero-init; last block resets -> replay-safe
__device__ unsigned g_ctr_cnt;

// ---------------- helpers ----------------
__device__ __forceinline__ float to_tf32(float x) {
    uint32_t r;
    asm("cvt.rn.tf32.f32 %0, %1;" : "=r"(r) : "f"(x));
    return __uint_as_float(r);
}
__device__ __forceinline__ void red_add_v4(float* a, float4 v) {
    asm volatile("red.global.add.v4.f32 [%0], {%1,%2,%3,%4};"
                 :: "l"(a), "f"(v.x), "f"(v.y), "f"(v.z), "f"(v.w) : "memory");
}
__device__ __forceinline__ void mma_tf32(float* c, const uint32_t* a,
                                         uint32_t b0, uint32_t b1) {
    asm volatile(
        "mma.sync.aligned.m16n8k8.row.col.f32.tf32.tf32.f32 "
        "{%0,%1,%2,%3}, {%4,%5,%6,%7}, {%8,%9}, {%0,%1,%2,%3};"
        : "+f"(c[0]), "+f"(c[1]), "+f"(c[2]), "+f"(c[3])
        : "r"(a[0]), "r"(a[1]), "r"(a[2]), "r"(a[3]), "r"(b0), "r"(b1));
}

// ---------------- simple kernels ----------------
__global__ void k_zero(float* __restrict__ p, int n4) {
    int t = blockIdx.x * blockDim.x + threadIdx.x;
    if (t < n4) reinterpret_cast<float4*>(p)[t] = make_float4(0.f, 0.f, 0.f, 0.f);
}

// smem-histogram count + fused inverse-count (last block)
__global__ void __launch_bounds__(1024) k_count(
    const int* __restrict__ bu, const int* __restrict__ bi,
    float* __restrict__ cnt, float* __restrict__ inv) {
    __shared__ int h[GC];
    for (int i = threadIdx.x; i < GC; i += 1024) h[i] = 0;
    __syncthreads();
    for (int t = blockIdx.x * 1024 + threadIdx.x; t < NU + NI;
         t += gridDim.x * 1024) {
        int b = (t < NU) ? bu[t] : bi[t - NU];
        atomicAdd(&h[b], 1);
    }
    __syncthreads();
    for (int i = threadIdx.x; i < GC; i += 1024)
        if (h[i]) atomicAdd(&cnt[i], (float)h[i]);
    __threadfence();
    __shared__ bool last;
    if (threadIdx.x == 0)
        last = (atomicAdd(&g_ctr_cnt, 1u) == gridDim.x - 1);
    __syncthreads();
    if (last) {
        if (threadIdx.x < GC)
            inv[threadIdx.x] = 1.0f / fmaxf(cnt[threadIdx.x], 1.0f);
        if (threadIdx.x == 0) g_ctr_cnt = 0;
    }
}

__global__ void k_build(const int* __restrict__ edge, int* __restrict__ deg,
                        int* __restrict__ csr) {
    int e = blockIdx.x * blockDim.x + threadIdx.x;
    if (e >= EC) return;
    int src = edge[e];
    int dst = edge[EC + e];
    int pos = atomicAdd(&deg[dst], 1);
    if (pos < DEGCAP) csr[(size_t)dst * DEGCAP + pos] = src;
}

// merged gather (both relations); block 0 zeroes this layer's BN stats
__global__ void k_gather(const float* __restrict__ xu, const float* __restrict__ xi,
                         float* __restrict__ aggU, float* __restrict__ aggI,
                         float* __restrict__ stats) {
    if (blockIdx.x == 0 && threadIdx.x < 128) {
#pragma unroll
        for (int i = 0; i < 4; i++) stats[threadIdx.x + i * 128] = 0.f;
    }
    int t = blockIdx.x * blockDim.x + threadIdx.x;
    int gn = t >> 5, lane = t & 31;
    if (gn >= 100000) return;
    const float* x;
    float* dst;
    const int* dp;
    const int* lst;
    int node;
    if (gn < 50000) {
        node = gn; x = xu; dst = aggI; dp = g_deg;
        lst = g_csr + (size_t)node * DEGCAP;
    } else {
        node = gn - 50000; x = xi; dst = aggU; dp = g_deg + 50000;
        lst = g_csr + 50000ull * DEGCAP + (size_t)node * DEGCAP;
    }
    int d = min(dp[node], DEGCAP);
    float ax = 0.f, ay = 0.f, az = 0.f, aw = 0.f;
    int j = 0;
    for (; j + 4 <= d; j += 4) {
        int s0 = lst[j], s1 = lst[j + 1], s2 = lst[j + 2], s3 = lst[j + 3];
        float4 v0 = *reinterpret_cast<const float4*>(&x[(size_t)s0 * FH + lane * 4]);
        float4 v1 = *reinterpret_cast<const float4*>(&x[(size_t)s1 * FH + lane * 4]);
        float4 v2 = *reinterpret_cast<const float4*>(&x[(size_t)s2 * FH + lane * 4]);
        float4 v3 = *reinterpret_cast<const float4*>(&x[(size_t)s3 * FH + lane * 4]);
        ax += v0.x + v1.x + v2.x + v3.x;
        ay += v0.y + v1.y + v2.y + v3.y;
        az += v0.z + v1.z + v2.z + v3.z;
        aw += v0.w + v1.w + v2.w + v3.w;
    }
    for (; j < d; j++) {
        int s = lst[j];
        float4 v = *reinterpret_cast<const float4*>(&x[(size_t)s * FH + lane * 4]);
        ax += v.x; ay += v.y; az += v.z; aw += v.w;
    }
    *reinterpret_cast<float4*>(&dst[(size_t)node * FH + lane * 4]) =
        make_float4(ax, ay, az, aw);
}

// ---------------- mma.sync tf32 GEMM, register-prefetch pipelined ----------------
// out[n,h] = sum_f A0[n,f]*Wa[h,f] + sum_f A1[n,f]*Wb[h,f] + bias[h]
// CTA 128x128, K=256 in 8 chunks of 32. Next chunk's LDGs issue before this
// chunk's MMAs so L2 latency hides behind tensor work.
__global__ void __launch_bounds__(256) k_gemm_mma(
    const float* __restrict__ aggI, const float* __restrict__ xI,
    const float* __restrict__ aggU, const float* __restrict__ xU,
    const float* __restrict__ WaI, const float* __restrict__ WbI,
    const float* __restrict__ WaU, const float* __restrict__ WbU,
    const float* __restrict__ bI, const float* __restrict__ bU,
    float* __restrict__ nI, float* __restrict__ nU) {
    __shared__ float sA[128 * 36];
    __shared__ float sW[128 * 36];

    int tid = threadIdx.x, wid = tid >> 5, lane = tid & 31;
    bool item = blockIdx.x < NT;
    int tile = item ? blockIdx.x : blockIdx.x - NT;
    const float* A0 = item ? aggI : aggU;
    const float* A1 = item ? xI : xU;
    const float* Wa = item ? WaI : WaU;
    const float* Wb = item ? WbI : WbU;
    const float* bias = item ? bI : bU;
    float* outp = item ? nI : nU;
    int row0 = tile * 128;

    int g = lane >> 2, q = lane & 3;
    int wm = wid & 3, wn = wid >> 2;
    int ar = tid >> 3, aj = tid & 7;      // staging coords (idx = i*256+tid)

    float c[2][8][4];
#pragma unroll
    for (int mt = 0; mt < 2; mt++)
#pragma unroll
        for (int nt = 0; nt < 8; nt++)
#pragma unroll
            for (int e = 0; e < 4; e++) c[mt][nt][e] = 0.f;

    float4 pa[4], pw[4];

    // prologue: fetch chunk 0
    {
        const float* Ap = A0;
        const float* Wp = Wa;
#pragma unroll
        for (int i = 0; i < 4; i++) {
            int r = ar + i * 32;
            pa[i] = (row0 + r < 50000)
                        ? *reinterpret_cast<const float4*>(
                              &Ap[(size_t)(row0 + r) * FH + aj * 4])
                        : make_float4(0.f, 0.f, 0.f, 0.f);
            pw[i] = *reinterpret_cast<const float4*>(&Wp[r * FH + aj * 4]);
        }
    }
#pragma unroll
    for (int i = 0; i < 4; i++) {
        int r = ar + i * 32;
        float4 va = pa[i], vw = pw[i];
        va.x = to_tf32(va.x); va.y = to_tf32(va.y);
        va.z = to_tf32(va.z); va.w = to_tf32(va.w);
        vw.x = to_tf32(vw.x); vw.y = to_tf32(vw.y);
        vw.z = to_tf32(vw.z); vw.w = to_tf32(vw.w);
        *reinterpret_cast<float4*>(&sA[r * 36 + aj * 4]) = va;
        *reinterpret_cast<float4*>(&sW[r * 36 + aj * 4]) = vw;
    }
    __syncthreads();

#pragma unroll 1
    for (int ch = 0; ch < 8; ch++) {
        // prefetch next chunk into registers (overlaps with MMAs below)
        if (ch < 7) {
            int cn = ch + 1;
            const float* Ap = (cn < 4) ? A0 : A1;
            const float* Wp = (cn < 4) ? Wa : Wb;
            int f0 = (cn & 3) * 32;
#pragma unroll
            for (int i = 0; i < 4; i++) {
                int r = ar + i * 32;
                pa[i] = (row0 + r < 50000)
                            ? *reinterpret_cast<const float4*>(
                                  &Ap[(size_t)(row0 + r) * FH + f0 + aj * 4])
                            : make_float4(0.f, 0.f, 0.f, 0.f);
                pw[i] = *reinterpret_cast<const float4*>(&Wp[r * FH + f0 + aj * 4]);
            }
        }

#pragma unroll
        for (int s = 0; s < 4; s++) {
            int k0 = s * 8;
            uint32_t a[2][4];
#pragma unroll
            for (int mt = 0; mt < 2; mt++) {
                int m0 = wm * 32 + mt * 16;
                a[mt][0] = __float_as_uint(sA[(m0 + g) * 36 + k0 + q]);
                a[mt][1] = __float_as_uint(sA[(m0 + g + 8) * 36 + k0 + q]);
                a[mt][2] = __float_as_uint(sA[(m0 + g) * 36 + k0 + q + 4]);
                a[mt][3] = __float_as_uint(sA[(m0 + g + 8) * 36 + k0 + q + 4]);
            }
#pragma unroll
            for (int nt = 0; nt < 8; nt++) {
                int n0 = wn * 64 + nt * 8;
                uint32_t b0 = __float_as_uint(sW[(n0 + g) * 36 + k0 + q]);
                uint32_t b1 = __float_as_uint(sW[(n0 + g) * 36 + k0 + q + 4]);
                mma_tf32(c[0][nt], a[0], b0, b1);
                mma_tf32(c[1][nt], a[1], b0, b1);
            }
        }
        __syncthreads();                  // everyone done reading this chunk

        if (ch < 7) {
#pragma unroll
            for (int i = 0; i < 4; i++) {
                int r = ar + i * 32;
                float4 va = pa[i], vw = pw[i];
                va.x = to_tf32(va.x); va.y = to_tf32(va.y);
                va.z = to_tf32(va.z); va.w = to_tf32(va.w);
                vw.x = to_tf32(vw.x); vw.y = to_tf32(vw.y);
                vw.z = to_tf32(vw.z); vw.w = to_tf32(vw.w);
                *reinterpret_cast<float4*>(&sA[r * 36 + aj * 4]) = va;
                *reinterpret_cast<float4*>(&sW[r * 36 + aj * 4]) = vw;
            }
            __syncthreads();
        }
    }

    // epilogue
#pragma unroll
    for (int nt = 0; nt < 8; nt++) {
        int n0 = wn * 64 + nt * 8 + 2 * q;
        float2 bb = *reinterpret_cast<const float2*>(&bias[n0]);
#pragma unroll
        for (int mt = 0; mt < 2; mt++) {
            int r = row0 + wm * 32 + mt * 16 + g;
            if (r < 50000) {
                float2 o = make_float2(c[mt][nt][0] + bb.x, c[mt][nt][1] + bb.y);
                *reinterpret_cast<float2*>(&outp[(size_t)r * FH + n0]) = o;
            }
            if (r + 8 < 50000) {
                float2 o = make_float2(c[mt][nt][2] + bb.x, c[mt][nt][3] + bb.y);
                *reinterpret_cast<float2*>(&outp[(size_t)(r + 8) * FH + n0]) = o;
            }
        }
    }
}

// ---------------- BN stats with fused bnparams (last-block) ----------------
__global__ void k_stats(const float* __restrict__ nu_, const float* __restrict__ ni_,
                        float* __restrict__ stats, float* __restrict__ bn,
                        const float* __restrict__ gu, const float* __restrict__ bu_,
                        const float* __restrict__ gi, const float* __restrict__ bi_) {
    int b = blockIdx.x;
    const float* v;
    float* s;
    int r0;
    if (b < NT) { v = nu_; s = stats; r0 = b * 128; }
    else { v = ni_; s = stats + 256; r0 = (b - NT) * 128; }
    int h = threadIdx.x;
    int re = min(r0 + 128, 50000);
    float a = 0.f, qq = 0.f;
    for (int r = r0; r < re; r++) {
        float x = fmaxf(v[(size_t)r * FH + h], 0.f);
        a += x;
        qq += x * x;
    }
    atomicAdd(&s[h], a);
    atomicAdd(&s[h + 128], qq);

    __threadfence();
    __shared__ bool last;
    if (threadIdx.x == 0)
        last = (atomicAdd(&g_ctr_stats, 1u) == 2 * NT - 1);
    __syncthreads();
    if (last) {
#pragma unroll
        for (int rep = 0; rep < 2; rep++) {
            int t2 = threadIdx.x + rep * 128;
            int hh = t2 & 127;
            const float* ss = (t2 < 128) ? stats : stats + 256;
            const float* g = (t2 < 128) ? gu : gi;
            const float* be = (t2 < 128) ? bu_ : bi_;
            float* o = (t2 < 128) ? bn : bn + 256;
            float invn = 1.0f / 50000.0f;
            float m = ss[hh] * invn;
            float var = ss[hh + 128] * invn - m * m;
            float sc = g[hh] * rsqrtf(var + BN_EPS);
            o[hh] = sc;
            o[hh + 128] = be[hh] - m * sc;
        }
        if (threadIdx.x == 0) g_ctr_stats = 0;
    }
}

__global__ void k_apply(const float* __restrict__ nu_, const float* __restrict__ ni_,
                        const float* __restrict__ bn, const int* __restrict__ bu,
                        const int* __restrict__ bi, const float* __restrict__ inv,
                        float* __restrict__ XU, float* __restrict__ XI,
                        float* __restrict__ pooled) {
    int t = blockIdx.x * blockDim.x + threadIdx.x;
    if (t >= (NU + NI) * 32) return;
    int gn = t >> 5, lane = t & 31;
    const float* v;
    const float* sc;
    const int* bt;
    float* xo;
    int r;
    if (gn < NU) { v = nu_; sc = bn; bt = bu; xo = XU; r = gn; }
    else { v = ni_; sc = bn + 256; bt = bi; xo = XI; r = gn - NU; }
    int g = bt[r];
    float ic = inv[g];
    float4 x = *reinterpret_cast<const float4*>(&v[(size_t)r * FH + lane * 4]);
    float4 s4 = *reinterpret_cast<const float4*>(&sc[lane * 4]);
    float4 h4 = *reinterpret_cast<const float4*>(&sc[128 + lane * 4]);
    float4 y;
    y.x = fmaxf(x.x, 0.f) * s4.x + h4.x;
    y.y = fmaxf(x.y, 0.f) * s4.y + h4.y;
    y.z = fmaxf(x.z, 0.f) * s4.z + h4.z;
    y.w = fmaxf(x.w, 0.f) * s4.w + h4.w;
    *reinterpret_cast<float4*>(&xo[(size_t)r * FH + lane * 4]) = y;
    red_add_v4(&pooled[(size_t)g * FH + lane * 4],
               make_float4(y.x * ic, y.y * ic, y.z * ic, y.w * ic));
}

__global__ void k_logits(const float* __restrict__ feats, const float* __restrict__ fcW,
                         const float* __restrict__ fcb, float* __restrict__ out) {
    int lg = blockIdx.x;
    int l = lg / GC;
    __shared__ float sf[FH];
    sf[threadIdx.x] = feats[(size_t)lg * FH + threadIdx.x];
    __syncthreads();
    int c = threadIdx.x;
    if (c < CC) {
        const float* w = &fcW[(size_t)(l * CC + c) * FH];
        float a = fcb[l * CC + c];
#pragma unroll 8
        for (int h = 0; h < FH; h++) a += sf[h] * w[h];
        out[(size_t)lg * CC + c] = a;
    }
}

// ---------------------------------------------------------------------------
extern "C" void kernel_launch(void* const* d_in, const int* in_sizes, int n_in,
                              void* d_out, int out_size) {
    const float* x_user    = (const float*)d_in[0];
    const float* x_item    = (const float*)d_in[1];
    const int*   e_u2i     = (const int*)d_in[2];
    const int*   e_i2u     = (const int*)d_in[3];
    const int*   b_user    = (const int*)d_in[4];
    const int*   b_item    = (const int*)d_in[5];
    const float* Wrel_u2i  = (const float*)d_in[6];
    const float* Wroot_u2i = (const float*)d_in[7];
    const float* bias_u2i  = (const float*)d_in[8];
    const float* Wrel_i2u  = (const float*)d_in[9];
    const float* Wroot_i2u = (const float*)d_in[10];
    const float* bias_i2u  = (const float*)d_in[11];
    const float* bng_u     = (const float*)d_in[12];
    const float* bnb_u     = (const float*)d_in[13];
    const float* bng_i     = (const float*)d_in[14];
    const float* bnb_i     = (const float*)d_in[15];
    const float* fcW       = (const float*)d_in[16];
    const float* fcb       = (const float*)d_in[17];
    float* out = (float*)d_out;

    float* buf = nullptr;
    cudaGetSymbolAddress((void**)&buf, g_buf);
    int* deg = nullptr;
    cudaGetSymbolAddress((void**)&deg, g_deg);
    int* csr = nullptr;
    cudaGetSymbolAddress((void**)&csr, g_csr);

    float* XU    = buf + OFF_XU;
    float* XI    = buf + OFF_XI;
    float* agg_u = buf + OFF_AGU;
    float* agg_i = buf + OFF_AGI;
    float* new_u = buf + OFF_NWU;
    float* new_i = buf + OFF_NWI;
    float* cnt   = buf + OFF_CNT;
    float* inv   = buf + OFF_INV;
    float* stats = buf + OFF_STATS;
    float* bn    = buf + OFF_BN;

    const int OUT_ELEMS = LC * GC * CC + LC * GC * FH;
    float* feats = out + LC * GC * CC;

    int* csr_u = csr + 50000ull * DEGCAP;

    k_zero<<<(100000 / 4 + 255) / 256, 256>>>((float*)deg, 100000 / 4);        // 0
    k_build<<<(EC + 255) / 256, 256>>>(e_u2i, deg, csr);                        // 1
    k_build<<<(EC + 255) / 256, 256>>>(e_i2u, deg + 50000, csr_u);              // 2
    k_gather<<<(100000 * 32 + 255) / 256, 256>>>(x_user, x_item, agg_u, agg_i,
                                                 stats);                        // 3 (ncu)
    k_zero<<<(OUT_ELEMS / 4 + 255) / 256, 256>>>(out, OUT_ELEMS / 4);           // 4
    k_zero<<<1, 128>>>(cnt, GC / 4);                                            // 5
    k_count<<<64, 1024>>>(b_user, b_item, cnt, inv);                            // 6

    const float* xu = x_user;
    const float* xi = x_item;

    for (int l = 0; l < LC; l++) {
        if (l > 0)
            k_gather<<<(100000 * 32 + 255) / 256, 256>>>(xu, xi, agg_u, agg_i, stats);
        size_t wo = (size_t)l * FH * FH;
        k_gemm_mma<<<2 * NT, 256>>>(agg_i, xi, agg_u, xu,
                                    Wrel_u2i + wo, Wroot_u2i + wo,
                                    Wrel_i2u + wo, Wroot_i2u + wo,
                                    bias_u2i + l * FH, bias_i2u + l * FH,
                                    new_i, new_u);
        k_stats<<<2 * NT, 128>>>(new_u, new_i, stats, bn,
                                 bng_u, bnb_u, bng_i, bnb_i);
        float* fl = feats + (size_t)l * GC * FH;
        k_apply<<<((NU + NI) * 32 + 255) / 256, 256>>>(new_u, new_i, bn, b_user,
                                                       b_item, inv, XU, XI, fl);
        xu = XU;
        xi = XI;
    }

    k_logits<<<LC * GC, FH>>>(feats, fcW, fcb, out);
}